// round 14
// baseline (speedup 1.0000x reference)
#include <cuda_runtime.h>
#include <cuda.h>
#include <cuda_fp16.h>
#include <cstdint>

// ============================================================================
// LSTM cell:  gates = [X|Hx] @ [Wih|Whh]^T + bias ; LSTM epilogue.
//   B=8192, I=H=1024  ->  GEMM M=8192, N=4096, K=2048.
//
// sm_100 (non-'a'): no tcgen05. TMA 4-stage ring -> ldmatrix -> mma.sync
// m16n8k16 fp16, fp32 accum, single fp16 pass (rel_err ~2e-4).
// PERSISTENT: grid = #SMs; each CTA loops over its (mt,nt) tiles with the
// TMA ring streaming k-tiles continuously across tile boundaries.
// CTA 128x256, 512 thr = 16 warps (2M x 8N), warp tile 64x32 (4 warps/SMSP).
// W rows permuted so gates interleave in groups of 8:
//   packed row r: gate=(r>>3)&3, h=(r>>5)*8 + (r&7)
// -> warp's 32-col span = [i|f|g|o] x 8 h; fused in-register LSTM epilogue.
// ============================================================================

#define BB     8192
#define HH     1024
#define KK     2048
#define NTOT   4096

#define TILE_M 128
#define TILE_N 256
#define TILE_K 64       // fp16 elems = 128 bytes = SW128 atom row
#define K_TILES (KK / TILE_K)   // 32
#define N_TILES_TOTAL ((BB / TILE_M) * (NTOT / TILE_N))   // 1024
#define STAGES  4

#define A_BYTES     (128 * 128)              // 16384
#define W_BYTES     (256 * 128)              // 32768
#define STAGE_BYTES (A_BYTES + W_BYTES)      // 49152
#define SM_A 0
#define SM_W 16384

#define SMEM_FULL0  0        // 4 x 8B
#define SMEM_EMPTY0 32       // 4 x 8B
#define SMEM_STAGE0 1024
#define SMEM_TOTAL  (SMEM_STAGE0 + STAGES * STAGE_BYTES)   // 197632

// ---------------- device scratch (no allocation allowed) -------------------
__device__ __align__(1024) __half g_A[(size_t)BB*KK];
__device__ __align__(1024) __half g_W[(size_t)NTOT*KK];
__device__ __align__(16)   float  g_bias_p[NTOT];

// ---------------- PTX helpers ----------------------------------------------
static __device__ __forceinline__ uint32_t smem_u32(const void* p) {
    uint32_t a;
    asm("{ .reg .u64 t; cvta.to.shared.u64 t, %1; cvt.u32.u64 %0, t; }"
        : "=r"(a) : "l"(p));
    return a;
}

#define MBARRIER_INIT(addr, cnt) \
    asm volatile("mbarrier.init.shared.b64 [%0], %1;" :: "r"((uint32_t)(addr)), "r"((uint32_t)(cnt)) : "memory")

#define MBARRIER_ARRIVE(addr) \
    asm volatile("mbarrier.arrive.shared.b64 _, [%0];" :: "r"((uint32_t)(addr)) : "memory")

#define MBARRIER_EXPECT_TX(addr, tx) \
    asm volatile("mbarrier.arrive.expect_tx.shared.b64 _, [%0], %1;" :: "r"((uint32_t)(addr)), "r"((uint32_t)(tx)) : "memory")

#define MBARRIER_WAIT_PARITY(addr, ph) do {                                   \
    uint32_t _m = (uint32_t)(addr); uint32_t _p = (uint32_t)(ph);             \
    asm volatile(                                                             \
        "{\n\t.reg .pred P1;\n\t"                                             \
        "WAIT_LOOP_%=:\n\t"                                                   \
        "mbarrier.try_wait.parity.acquire.cta.shared::cta.b64 P1, [%0], %1, 0x989680;\n\t" \
        "@P1 bra.uni WAIT_DONE_%=;\n\t"                                       \
        "bra.uni WAIT_LOOP_%=;\n\t"                                           \
        "WAIT_DONE_%=:\n\t}"                                                  \
        :: "r"(_m), "r"(_p) : "memory");                                      \
} while (0)

#define TMA_LOAD_3D(smem_addr, tmap, cx_, cy_, cz_, mbar)                      \
    asm volatile(                                                              \
        "cp.async.bulk.tensor.3d.shared::cta.global.tile.mbarrier::complete_tx::bytes " \
        "[%0], [%1, {%2, %3, %4}], [%5];"                                      \
        :: "r"((uint32_t)(smem_addr)), "l"(tmap), "r"((int32_t)(cx_)),         \
           "r"((int32_t)(cy_)), "r"((int32_t)(cz_)), "r"((uint32_t)(mbar))     \
        : "memory")

#define LDMATRIX_X4(r, addr)                                                   \
    asm volatile("ldmatrix.sync.aligned.m8n8.x4.shared.b16 {%0,%1,%2,%3}, [%4];" \
        : "=r"((r)[0]), "=r"((r)[1]), "=r"((r)[2]), "=r"((r)[3])               \
        : "r"(addr))

#define LDMATRIX_X4_B(b0, b1, addr)                                            \
    asm volatile("ldmatrix.sync.aligned.m8n8.x4.shared.b16 {%0,%1,%2,%3}, [%4];" \
        : "=r"((b0)[0]), "=r"((b0)[1]), "=r"((b1)[0]), "=r"((b1)[1])           \
        : "r"(addr))

#define MMA_F16(d, a, b)                                                       \
    asm volatile("mma.sync.aligned.m16n8k16.row.col.f32.f16.f16.f32 "          \
        "{%0,%1,%2,%3}, {%4,%5,%6,%7}, {%8,%9}, {%0,%1,%2,%3};"                \
        : "+f"((d)[0]), "+f"((d)[1]), "+f"((d)[2]), "+f"((d)[3])               \
        : "r"((a)[0]), "r"((a)[1]), "r"((a)[2]), "r"((a)[3]),                  \
          "r"((b)[0]), "r"((b)[1]))

static __device__ __forceinline__ float fsigmoid(float x) {
    return 1.0f / (1.0f + __expf(-x));
}
static __device__ __forceinline__ float ftanh(float x) {
    return 2.0f / (1.0f + __expf(-2.0f * x)) - 1.0f;
}

// ============================================================================
// Kernel 1: pack fp32 -> fp16, concat K, permute W rows, gather bias.
// Packed W row r: gate=(r>>3)&3, h=(r>>5)*8 + (r&7) -> orig = gate*1024 + h.
// ============================================================================
__global__ __launch_bounds__(512) void lstm_pack_kernel(
    const float* __restrict__ input, const float* __restrict__ hx,
    const float* __restrict__ wih,   const float* __restrict__ whh,
    const float* __restrict__ bias)
{
    int row = blockIdx.x;
    int c4  = threadIdx.x * 4;          // 0..2044
    const float* src;
    __half* dst;

    if (row < BB) {
        src = (c4 < HH) ? (input + (size_t)row * HH + c4)
                        : (hx    + (size_t)row * HH + (c4 - HH));
        dst = g_A + (size_t)row * KK + c4;
    } else {
        int r    = row - BB;
        int orig = ((r >> 3) & 3) * 1024 + ((r >> 5) * 8) + (r & 7);
        src = (c4 < HH) ? (wih + (size_t)orig * HH + c4)
                        : (whh + (size_t)orig * HH + (c4 - HH));
        dst = g_W + (size_t)r * KK + c4;
        if (threadIdx.x == 0) g_bias_p[r] = bias[orig];
    }

    float4 v = *reinterpret_cast<const float4*>(src);
    __half2 w01; w01.x = __float2half(v.x); w01.y = __float2half(v.y);
    __half2 w23; w23.x = __float2half(v.z); w23.y = __float2half(v.w);
    reinterpret_cast<__half2*>(dst)[0] = w01;
    reinterpret_cast<__half2*>(dst)[1] = w23;
}

// ============================================================================
// Kernel 2: persistent mma.sync fp16 GEMM + fused LSTM epilogue.
// Grid: #SMs CTAs, 512 threads (16 warps, 2(M) x 8(N)), warp tile 64x32.
// CTA processes tiles blockIdx.x, +grid, +2*grid, ... with one continuous
// TMA ring over the concatenated k-stream of all its tiles.
// ============================================================================
__global__ __launch_bounds__(512, 1) void lstm_gemm_kernel(
    const __grid_constant__ CUtensorMap mapA,
    const __grid_constant__ CUtensorMap mapW,
    const float* __restrict__ cx,
    float* __restrict__ out)
{
    extern __shared__ char smem[];
    const uint32_t sb = smem_u32(smem);
    const int tid  = threadIdx.x;
    const int lane = tid & 31;
    const int wid  = tid >> 5;
    const int wm   = wid >> 3;     // warp row (0-1): 64 rows each
    const int wn   = wid & 7;      // warp col (0-7): 32 cols each

    if (tid == 0) {
#pragma unroll
        for (int s = 0; s < STAGES; s++) {
            MBARRIER_INIT(sb + SMEM_FULL0  + s * 8, 1);
            MBARRIER_INIT(sb + SMEM_EMPTY0 + s * 8, 16);  // one arrive per warp
        }
    }
    __syncthreads();

    const int n_my    = (N_TILES_TOTAL - blockIdx.x + gridDim.x - 1) / gridDim.x;
    const int total_g = n_my * K_TILES;

    // prologue: tid0 fills the ring
    if (tid == 0) {
#pragma unroll
        for (int p = 0; p < STAGES; p++) {
            if (p < total_g) {
                const int tl  = blockIdx.x + (p >> 5) * gridDim.x;
                const uint32_t st = sb + SMEM_STAGE0 + p * STAGE_BYTES;
                const uint32_t fb = sb + SMEM_FULL0 + p * 8;
                MBARRIER_EXPECT_TX(fb, STAGE_BYTES);
                TMA_LOAD_3D(st + SM_A, &mapA, (p & 31) * TILE_K,
                            (tl >> 4) * TILE_M, 0, fb);
                TMA_LOAD_3D(st + SM_W, &mapW, (p & 31) * TILE_K,
                            (tl & 15) * TILE_N, 0, fb);
            }
        }
    }

    // ---- precomputed ldmatrix addressing (SW128: 16B chunk ^= row&7) -------
    const int aChX = lane >> 4;
    const int bChX = (lane >> 3) & 1;
    const int sXor = lane & 7;
    const int aRow = wm * 64 + (lane & 15);
    const int bN   = (lane & 7) + ((lane >> 4) << 3);

    uint32_t aOff[4], bOff[2], chA[4], chB[4];
#pragma unroll
    for (int mt = 0; mt < 4; mt++) aOff[mt] = SM_A + (aRow + mt * 16) * 128;
#pragma unroll
    for (int q = 0; q < 2; q++)   bOff[q]  = SM_W + (wn * 32 + q * 16 + bN) * 128;
#pragma unroll
    for (int ks = 0; ks < 4; ks++) {
        chA[ks] = (uint32_t)(((ks * 2 + aChX) ^ sXor) << 4);
        chB[ks] = (uint32_t)(((ks * 2 + bChX) ^ sXor) << 4);
    }

    int fph[STAGES] = {0, 0, 0, 0}, eph[STAGES] = {0, 0, 0, 0};
    int g = 0;

    for (int ti = 0; ti < n_my; ti++) {
        const int tile = blockIdx.x + ti * gridDim.x;

        float d[4][4][4];                      // [mt][gate][frag]
#pragma unroll
        for (int a = 0; a < 4; a++)
#pragma unroll
            for (int b = 0; b < 4; b++)
#pragma unroll
                for (int c = 0; c < 4; c++) d[a][b][c] = 0.0f;

        for (int t = 0; t < K_TILES; t++, g++) {
            const int s = g & (STAGES - 1);
            const uint32_t stBase = sb + SMEM_STAGE0 + s * STAGE_BYTES;
            MBARRIER_WAIT_PARITY(sb + SMEM_FULL0 + s * 8, fph[s]);
            fph[s] ^= 1;

#pragma unroll
            for (int ks = 0; ks < 4; ks++) {
                const uint32_t sA = stBase + chA[ks];
                const uint32_t sB = stBase + chB[ks];
                uint32_t a[4][4], bw[4][2];
#pragma unroll
                for (int mt = 0; mt < 4; mt++)
                    LDMATRIX_X4(a[mt], sA + aOff[mt]);
#pragma unroll
                for (int q = 0; q < 2; q++)
                    LDMATRIX_X4_B(bw[q*2], bw[q*2 + 1], sB + bOff[q]);
#pragma unroll
                for (int mt = 0; mt < 4; mt++)
#pragma unroll
                    for (int gg = 0; gg < 4; gg++)
                        MMA_F16(d[mt][gg], a[mt], bw[gg]);
            }

            if (lane == 0) MBARRIER_ARRIVE(sb + SMEM_EMPTY0 + s * 8);
            if (tid == 0 && g + STAGES < total_g) {
                MBARRIER_WAIT_PARITY(sb + SMEM_EMPTY0 + s * 8, eph[s]);
                eph[s] ^= 1;
                const int gp  = g + STAGES;
                const int tl  = blockIdx.x + (gp >> 5) * gridDim.x;
                const uint32_t fb = sb + SMEM_FULL0 + s * 8;
                MBARRIER_EXPECT_TX(fb, STAGE_BYTES);
                TMA_LOAD_3D(stBase + SM_A, &mapA, (gp & 31) * TILE_K,
                            (tl >> 4) * TILE_M, 0, fb);
                TMA_LOAD_3D(stBase + SM_W, &mapW, (gp & 31) * TILE_K,
                            (tl & 15) * TILE_N, 0, fb);
            }
        }

        // ---------------- fused in-register LSTM epilogue --------------------
        // Warp's 32 cols = [i|f|g|o] x 8 h;  h-block = nt_blk*8 + wn.
        const int m0     = (tile >> 4) * TILE_M;
        const int wr0    = (tile & 15) * TILE_N;
        const int rbase  = m0 + wm * 64 + (lane >> 2);
        const int h_base = ((tile & 15) * 8 + wn) * 8 + 2 * (lane & 3);
        const int bcol   = wr0 + wn * 32 + 2 * (lane & 3);

        const float2 bi = *reinterpret_cast<const float2*>(g_bias_p + bcol);
        const float2 bf = *reinterpret_cast<const float2*>(g_bias_p + bcol + 8);
        const float2 bg = *reinterpret_cast<const float2*>(g_bias_p + bcol + 16);
        const float2 bo = *reinterpret_cast<const float2*>(g_bias_p + bcol + 24);

#pragma unroll
        for (int mt = 0; mt < 4; mt++) {
#pragma unroll
            for (int half = 0; half < 2; half++) {
                const int r = rbase + mt * 16 + half * 8;
                const float2 c2 = *reinterpret_cast<const float2*>(
                    cx + (size_t)r * HH + h_base);
                float hyv[2], cyv[2];
#pragma unroll
                for (int j = 0; j < 2; j++) {
                    const int fi = half * 2 + j;
                    float gi = d[mt][0][fi] + (j ? bi.y : bi.x);
                    float gf = d[mt][1][fi] + (j ? bf.y : bf.x);
                    float gg = d[mt][2][fi] + (j ? bg.y : bg.x);
                    float go = d[mt][3][fi] + (j ? bo.y : bo.x);
                    float iv = fsigmoid(gi);
                    float fv = fsigmoid(gf);
                    float gv = ftanh(gg);
                    float ov = fsigmoid(go);
                    float cxv = (j == 0) ? c2.x : c2.y;
                    float cn = fv * cxv + iv * gv;
                    cyv[j] = cn;
                    hyv[j] = ov * ftanh(cn);
                }
                *reinterpret_cast<float2*>(out + (size_t)r * HH + h_base) =
                    make_float2(hyv[0], hyv[1]);
                *reinterpret_cast<float2*>(out + (size_t)BB * HH +
                                           (size_t)r * HH + h_base) =
                    make_float2(cyv[0], cyv[1]);
            }
        }
    }
}

// ============================================================================
// Host launch
// ============================================================================
typedef CUresult (*cuTensorMapEncodeTiled_t)(
    CUtensorMap*, CUtensorMapDataType, cuuint32_t, void*,
    const cuuint64_t*, const cuuint64_t*, const cuuint32_t*, const cuuint32_t*,
    CUtensorMapInterleave, CUtensorMapSwizzle, CUtensorMapL2promotion,
    CUtensorMapFloatOOBfill);

static void encode_map(cuTensorMapEncodeTiled_t fn, CUtensorMap* m, void* base,
                       unsigned long long rows, unsigned box_rows)
{
    cuuint64_t dims[3]    = {(cuuint64_t)KK, rows, 1};
    cuuint64_t strides[2] = {(cuuint64_t)KK * 2, rows * (cuuint64_t)KK * 2};
    cuuint32_t box[3]     = {TILE_K, box_rows, 1};
    cuuint32_t es[3]      = {1, 1, 1};
    fn(m, CU_TENSOR_MAP_DATA_TYPE_FLOAT16, 3, base, dims, strides, box, es,
       CU_TENSOR_MAP_INTERLEAVE_NONE, CU_TENSOR_MAP_SWIZZLE_128B,
       CU_TENSOR_MAP_L2_PROMOTION_L2_128B, CU_TENSOR_MAP_FLOAT_OOB_FILL_NONE);
}

extern "C" void kernel_launch(void* const* d_in, const int* in_sizes, int n_in,
                              void* d_out, int out_size)
{
    const float* input = (const float*)d_in[0];
    const float* hx    = (const float*)d_in[1];
    const float* cx    = (const float*)d_in[2];
    const float* wih   = (const float*)d_in[3];
    const float* whh   = (const float*)d_in[4];
    const float* bias  = (const float*)d_in[5];
    float* out = (float*)d_out;
    (void)in_sizes; (void)n_in; (void)out_size;

    void *pA, *pW;
    cudaGetSymbolAddress(&pA, g_A);
    cudaGetSymbolAddress(&pW, g_W);

    cuTensorMapEncodeTiled_t enc = nullptr;
    cudaDriverEntryPointQueryResult qr;
    cudaGetDriverEntryPoint("cuTensorMapEncodeTiled", (void**)&enc,
                            cudaEnableDefault, &qr);

    CUtensorMap mA, mW;
    encode_map(enc, &mA, pA, BB,   128);
    encode_map(enc, &mW, pW, NTOT, 256);

    int nsm = 0;
    cudaDeviceGetAttribute(&nsm, cudaDevAttrMultiProcessorCount, 0);
    if (nsm <= 0) nsm = 148;
    if (nsm > N_TILES_TOTAL) nsm = N_TILES_TOTAL;

    lstm_pack_kernel<<<BB + NTOT, 512>>>(input, hx, wih, whh, bias);

    cudaFuncSetAttribute(lstm_gemm_kernel,
                         cudaFuncAttributeMaxDynamicSharedMemorySize, SMEM_TOTAL);
    lstm_gemm_kernel<<<nsm, 512, SMEM_TOTAL>>>(mA, mW, cx, out);
}

// round 17
// speedup vs baseline: 1.0008x; 1.0008x over previous
#include <cuda_runtime.h>
#include <cuda.h>
#include <cuda_fp16.h>
#include <cstdint>

// ============================================================================
// LSTM cell:  gates = [X|Hx] @ [Wih|Whh]^T + bias ; LSTM epilogue.
//   B=8192, I=H=1024  ->  GEMM M=8192, N=4096, K=2048.
//
// sm_100 (non-'a'): no tcgen05. TMA 3-stage ring -> ldmatrix -> mma.sync
// m16n8k16 fp16, fp32 accum, single fp16 pass (rel_err ~2e-4).
// PERSISTENT, 2 CTAs/SM for desynchronized barrier domains: each CTA 128x128,
// 256 thr = 8 warps (2M x 4N), warp tile 64x32. While one CTA's warps are in
// their k-tile-boundary LDSM burst, the co-resident CTA's warps feed HMMAs.
// W rows permuted so gates interleave in groups of 8:
//   packed row r: gate=(r>>3)&3, h=(r>>5)*8 + (r&7)
// -> warp's 32-col span = [i|f|g|o] x 8 h; fused in-register LSTM epilogue.
// ============================================================================

#define BB     8192
#define HH     1024
#define KK     2048
#define NTOT   4096

#define TILE_M 128
#define TILE_N 128
#define TILE_K 64       // fp16 elems = 128 bytes = SW128 atom row
#define K_TILES (KK / TILE_K)   // 32
#define N_TILES_TOTAL ((BB / TILE_M) * (NTOT / TILE_N))   // 2048
#define STAGES  3

#define A_BYTES     (128 * 128)              // 16384
#define W_BYTES     (128 * 128)              // 16384
#define STAGE_BYTES (A_BYTES + W_BYTES)      // 32768
#define SM_A 0
#define SM_W 16384

#define SMEM_FULL0  0        // 3 x 8B
#define SMEM_EMPTY0 24       // 3 x 8B
#define SMEM_STAGE0 1024
#define SMEM_TOTAL  (SMEM_STAGE0 + STAGES * STAGE_BYTES)   // 99328

// ---------------- device scratch (no allocation allowed) -------------------
__device__ __align__(1024) __half g_A[(size_t)BB*KK];
__device__ __align__(1024) __half g_W[(size_t)NTOT*KK];
__device__ __align__(16)   float  g_bias_p[NTOT];

// ---------------- PTX helpers ----------------------------------------------
static __device__ __forceinline__ uint32_t smem_u32(const void* p) {
    uint32_t a;
    asm("{ .reg .u64 t; cvta.to.shared.u64 t, %1; cvt.u32.u64 %0, t; }"
        : "=r"(a) : "l"(p));
    return a;
}

#define MBARRIER_INIT(addr, cnt) \
    asm volatile("mbarrier.init.shared.b64 [%0], %1;" :: "r"((uint32_t)(addr)), "r"((uint32_t)(cnt)) : "memory")

#define MBARRIER_ARRIVE(addr) \
    asm volatile("mbarrier.arrive.shared.b64 _, [%0];" :: "r"((uint32_t)(addr)) : "memory")

#define MBARRIER_EXPECT_TX(addr, tx) \
    asm volatile("mbarrier.arrive.expect_tx.shared.b64 _, [%0], %1;" :: "r"((uint32_t)(addr)), "r"((uint32_t)(tx)) : "memory")

#define MBARRIER_WAIT_PARITY(addr, ph) do {                                   \
    uint32_t _m = (uint32_t)(addr); uint32_t _p = (uint32_t)(ph);             \
    asm volatile(                                                             \
        "{\n\t.reg .pred P1;\n\t"                                             \
        "WAIT_LOOP_%=:\n\t"                                                   \
        "mbarrier.try_wait.parity.acquire.cta.shared::cta.b64 P1, [%0], %1, 0x989680;\n\t" \
        "@P1 bra.uni WAIT_DONE_%=;\n\t"                                       \
        "bra.uni WAIT_LOOP_%=;\n\t"                                           \
        "WAIT_DONE_%=:\n\t}"                                                  \
        :: "r"(_m), "r"(_p) : "memory");                                      \
} while (0)

#define TMA_LOAD_3D(smem_addr, tmap, cx_, cy_, cz_, mbar)                      \
    asm volatile(                                                              \
        "cp.async.bulk.tensor.3d.shared::cta.global.tile.mbarrier::complete_tx::bytes " \
        "[%0], [%1, {%2, %3, %4}], [%5];"                                      \
        :: "r"((uint32_t)(smem_addr)), "l"(tmap), "r"((int32_t)(cx_)),         \
           "r"((int32_t)(cy_)), "r"((int32_t)(cz_)), "r"((uint32_t)(mbar))     \
        : "memory")

#define LDMATRIX_X4(r, addr)                                                   \
    asm volatile("ldmatrix.sync.aligned.m8n8.x4.shared.b16 {%0,%1,%2,%3}, [%4];" \
        : "=r"((r)[0]), "=r"((r)[1]), "=r"((r)[2]), "=r"((r)[3])               \
        : "r"(addr))

#define LDMATRIX_X4_B(b0, b1, addr)                                            \
    asm volatile("ldmatrix.sync.aligned.m8n8.x4.shared.b16 {%0,%1,%2,%3}, [%4];" \
        : "=r"((b0)[0]), "=r"((b0)[1]), "=r"((b1)[0]), "=r"((b1)[1])           \
        : "r"(addr))

#define MMA_F16(d, a, b)                                                       \
    asm volatile("mma.sync.aligned.m16n8k16.row.col.f32.f16.f16.f32 "          \
        "{%0,%1,%2,%3}, {%4,%5,%6,%7}, {%8,%9}, {%0,%1,%2,%3};"                \
        : "+f"((d)[0]), "+f"((d)[1]), "+f"((d)[2]), "+f"((d)[3])               \
        : "r"((a)[0]), "r"((a)[1]), "r"((a)[2]), "r"((a)[3]),                  \
          "r"((b)[0]), "r"((b)[1]))

static __device__ __forceinline__ float fsigmoid(float x) {
    return 1.0f / (1.0f + __expf(-x));
}
static __device__ __forceinline__ float ftanh(float x) {
    return 2.0f / (1.0f + __expf(-2.0f * x)) - 1.0f;
}

// ============================================================================
// Kernel 1: pack fp32 -> fp16, concat K, permute W rows, gather bias.
// Packed W row r: gate=(r>>3)&3, h=(r>>5)*8 + (r&7) -> orig = gate*1024 + h.
// ============================================================================
__global__ __launch_bounds__(512) void lstm_pack_kernel(
    const float* __restrict__ input, const float* __restrict__ hx,
    const float* __restrict__ wih,   const float* __restrict__ whh,
    const float* __restrict__ bias)
{
    int row = blockIdx.x;
    int c4  = threadIdx.x * 4;          // 0..2044
    const float* src;
    __half* dst;

    if (row < BB) {
        src = (c4 < HH) ? (input + (size_t)row * HH + c4)
                        : (hx    + (size_t)row * HH + (c4 - HH));
        dst = g_A + (size_t)row * KK + c4;
    } else {
        int r    = row - BB;
        int orig = ((r >> 3) & 3) * 1024 + ((r >> 5) * 8) + (r & 7);
        src = (c4 < HH) ? (wih + (size_t)orig * HH + c4)
                        : (whh + (size_t)orig * HH + (c4 - HH));
        dst = g_W + (size_t)r * KK + c4;
        if (threadIdx.x == 0) g_bias_p[r] = bias[orig];
    }

    float4 v = *reinterpret_cast<const float4*>(src);
    __half2 w01; w01.x = __float2half(v.x); w01.y = __float2half(v.y);
    __half2 w23; w23.x = __float2half(v.z); w23.y = __float2half(v.w);
    reinterpret_cast<__half2*>(dst)[0] = w01;
    reinterpret_cast<__half2*>(dst)[1] = w23;
}

// ============================================================================
// Kernel 2: persistent mma.sync fp16 GEMM + fused LSTM epilogue.
// Grid: 2 x #SMs CTAs (2 co-resident CTAs/SM), 256 threads (8 warps, 2M x 4N),
// warp tile 64x32. Each CTA streams k-tiles of its tiles through a private
// 3-stage TMA ring -> independent barrier domains desynchronize the two CTAs.
// ============================================================================
__global__ __launch_bounds__(256, 2) void lstm_gemm_kernel(
    const __grid_constant__ CUtensorMap mapA,
    const __grid_constant__ CUtensorMap mapW,
    const float* __restrict__ cx,
    float* __restrict__ out)
{
    extern __shared__ char smem[];
    const uint32_t sb = smem_u32(smem);
    const int tid  = threadIdx.x;
    const int lane = tid & 31;
    const int wid  = tid >> 5;
    const int wm   = wid >> 2;     // warp row (0-1): 64 rows each
    const int wn   = wid & 3;      // warp col (0-3): 32 cols each

    if (tid == 0) {
#pragma unroll
        for (int s = 0; s < STAGES; s++) {
            MBARRIER_INIT(sb + SMEM_FULL0  + s * 8, 1);
            MBARRIER_INIT(sb + SMEM_EMPTY0 + s * 8, 8);   // one arrive per warp
        }
    }
    __syncthreads();

    const int n_my    = (N_TILES_TOTAL - blockIdx.x + gridDim.x - 1) / gridDim.x;
    const int total_g = n_my * K_TILES;

    // prologue: tid0 fills the ring (total_g >= K_TILES > STAGES always)
    if (tid == 0) {
#pragma unroll
        for (int p = 0; p < STAGES; p++) {
            const int tl  = blockIdx.x + (p >> 5) * gridDim.x;
            const uint32_t st = sb + SMEM_STAGE0 + p * STAGE_BYTES;
            const uint32_t fb = sb + SMEM_FULL0 + p * 8;
            MBARRIER_EXPECT_TX(fb, STAGE_BYTES);
            TMA_LOAD_3D(st + SM_A, &mapA, (p & 31) * TILE_K,
                        (tl >> 5) * TILE_M, 0, fb);
            TMA_LOAD_3D(st + SM_W, &mapW, (p & 31) * TILE_K,
                        (tl & 31) * TILE_N, 0, fb);
        }
    }

    // ---- precomputed ldmatrix addressing (SW128: 16B chunk ^= row&7) -------
    const int aChX = lane >> 4;
    const int bChX = (lane >> 3) & 1;
    const int sXor = lane & 7;
    const int aRow = wm * 64 + (lane & 15);
    const int bN   = (lane & 7) + ((lane >> 4) << 3);

    uint32_t aOff[4], bOff[2], chA[4], chB[4];
#pragma unroll
    for (int mt = 0; mt < 4; mt++) aOff[mt] = SM_A + (aRow + mt * 16) * 128;
#pragma unroll
    for (int q = 0; q < 2; q++)   bOff[q]  = SM_W + (wn * 32 + q * 16 + bN) * 128;
#pragma unroll
    for (int ks = 0; ks < 4; ks++) {
        chA[ks] = (uint32_t)(((ks * 2 + aChX) ^ sXor) << 4);
        chB[ks] = (uint32_t)(((ks * 2 + bChX) ^ sXor) << 4);
    }

    int fph[STAGES] = {0, 0, 0}, eph[STAGES] = {0, 0, 0};
    int g = 0, s = 0;   // s = g % STAGES

    for (int ti = 0; ti < n_my; ti++) {
        const int tile = blockIdx.x + ti * gridDim.x;

        float d[4][4][4];                      // [mt][gate][frag]
#pragma unroll
        for (int a = 0; a < 4; a++)
#pragma unroll
            for (int b = 0; b < 4; b++)
#pragma unroll
                for (int c = 0; c < 4; c++) d[a][b][c] = 0.0f;

        for (int t = 0; t < K_TILES; t++, g++) {
            const uint32_t stBase = sb + SMEM_STAGE0 + s * STAGE_BYTES;
            MBARRIER_WAIT_PARITY(sb + SMEM_FULL0 + s * 8, fph[s]);
            fph[s] ^= 1;

#pragma unroll
            for (int ks = 0; ks < 4; ks++) {
                const uint32_t sA = stBase + chA[ks];
                const uint32_t sB = stBase + chB[ks];
                uint32_t a[4][4], bw[4][2];
#pragma unroll
                for (int q = 0; q < 2; q++)
                    LDMATRIX_X4_B(bw[q*2], bw[q*2 + 1], sB + bOff[q]);
#pragma unroll
                for (int mt = 0; mt < 4; mt++)
                    LDMATRIX_X4(a[mt], sA + aOff[mt]);
#pragma unroll
                for (int mt = 0; mt < 4; mt++)
#pragma unroll
                    for (int gg = 0; gg < 4; gg++)
                        MMA_F16(d[mt][gg], a[mt], bw[gg]);
            }

            if (lane == 0) MBARRIER_ARRIVE(sb + SMEM_EMPTY0 + s * 8);
            if (tid == 0 && g + STAGES < total_g) {
                MBARRIER_WAIT_PARITY(sb + SMEM_EMPTY0 + s * 8, eph[s]);
                eph[s] ^= 1;
                const int gp  = g + STAGES;
                const int tl  = blockIdx.x + (gp >> 5) * gridDim.x;
                const uint32_t fb = sb + SMEM_FULL0 + s * 8;
                MBARRIER_EXPECT_TX(fb, STAGE_BYTES);
                TMA_LOAD_3D(stBase + SM_A, &mapA, (gp & 31) * TILE_K,
                            (tl >> 5) * TILE_M, 0, fb);
                TMA_LOAD_3D(stBase + SM_W, &mapW, (gp & 31) * TILE_K,
                            (tl & 31) * TILE_N, 0, fb);
            }
            if (++s == STAGES) s = 0;
        }

        // ---------------- fused in-register LSTM epilogue --------------------
        // Warp's 32 cols = [i|f|g|o] x 8 h;  h-block = (tile&31)*4 + wn.
        const int m0     = (tile >> 5) * TILE_M;
        const int wr0    = (tile & 31) * TILE_N;
        const int rbase  = m0 + wm * 64 + (lane >> 2);
        const int h_base = ((tile & 31) * 4 + wn) * 8 + 2 * (lane & 3);
        const int bcol   = wr0 + wn * 32 + 2 * (lane & 3);

        const float2 bi = *reinterpret_cast<const float2*>(g_bias_p + bcol);
        const float2 bf = *reinterpret_cast<const float2*>(g_bias_p + bcol + 8);
        const float2 bg = *reinterpret_cast<const float2*>(g_bias_p + bcol + 16);
        const float2 bo = *reinterpret_cast<const float2*>(g_bias_p + bcol + 24);

#pragma unroll
        for (int mt = 0; mt < 4; mt++) {
#pragma unroll
            for (int half = 0; half < 2; half++) {
                const int r = rbase + mt * 16 + half * 8;
                const float2 c2 = *reinterpret_cast<const float2*>(
                    cx + (size_t)r * HH + h_base);
                float hyv[2], cyv[2];
#pragma unroll
                for (int j = 0; j < 2; j++) {
                    const int fi = half * 2 + j;
                    float gi = d[mt][0][fi] + (j ? bi.y : bi.x);
                    float gf = d[mt][1][fi] + (j ? bf.y : bf.x);
                    float gg = d[mt][2][fi] + (j ? bg.y : bg.x);
                    float go = d[mt][3][fi] + (j ? bo.y : bo.x);
                    float iv = fsigmoid(gi);
                    float fv = fsigmoid(gf);
                    float gv = ftanh(gg);
                    float ov = fsigmoid(go);
                    float cxv = (j == 0) ? c2.x : c2.y;
                    float cn = fv * cxv + iv * gv;
                    cyv[j] = cn;
                    hyv[j] = ov * ftanh(cn);
                }
                *reinterpret_cast<float2*>(out + (size_t)r * HH + h_base) =
                    make_float2(hyv[0], hyv[1]);
                *reinterpret_cast<float2*>(out + (size_t)BB * HH +
                                           (size_t)r * HH + h_base) =
                    make_float2(cyv[0], cyv[1]);
            }
        }
    }
}

// ============================================================================
// Host launch
// ============================================================================
typedef CUresult (*cuTensorMapEncodeTiled_t)(
    CUtensorMap*, CUtensorMapDataType, cuuint32_t, void*,
    const cuuint64_t*, const cuuint64_t*, const cuuint32_t*, const cuuint32_t*,
    CUtensorMapInterleave, CUtensorMapSwizzle, CUtensorMapL2promotion,
    CUtensorMapFloatOOBfill);

static void encode_map(cuTensorMapEncodeTiled_t fn, CUtensorMap* m, void* base,
                       unsigned long long rows, unsigned box_rows)
{
    cuuint64_t dims[3]    = {(cuuint64_t)KK, rows, 1};
    cuuint64_t strides[2] = {(cuuint64_t)KK * 2, rows * (cuuint64_t)KK * 2};
    cuuint32_t box[3]     = {TILE_K, box_rows, 1};
    cuuint32_t es[3]      = {1, 1, 1};
    fn(m, CU_TENSOR_MAP_DATA_TYPE_FLOAT16, 3, base, dims, strides, box, es,
       CU_TENSOR_MAP_INTERLEAVE_NONE, CU_TENSOR_MAP_SWIZZLE_128B,
       CU_TENSOR_MAP_L2_PROMOTION_L2_128B, CU_TENSOR_MAP_FLOAT_OOB_FILL_NONE);
}

extern "C" void kernel_launch(void* const* d_in, const int* in_sizes, int n_in,
                              void* d_out, int out_size)
{
    const float* input = (const float*)d_in[0];
    const float* hx    = (const float*)d_in[1];
    const float* cx    = (const float*)d_in[2];
    const float* wih   = (const float*)d_in[3];
    const float* whh   = (const float*)d_in[4];
    const float* bias  = (const float*)d_in[5];
    float* out = (float*)d_out;
    (void)in_sizes; (void)n_in; (void)out_size;

    void *pA, *pW;
    cudaGetSymbolAddress(&pA, g_A);
    cudaGetSymbolAddress(&pW, g_W);

    cuTensorMapEncodeTiled_t enc = nullptr;
    cudaDriverEntryPointQueryResult qr;
    cudaGetDriverEntryPoint("cuTensorMapEncodeTiled", (void**)&enc,
                            cudaEnableDefault, &qr);

    CUtensorMap mA, mW;
    encode_map(enc, &mA, pA, BB,   128);
    encode_map(enc, &mW, pW, NTOT, 128);

    int nsm = 0;
    cudaDeviceGetAttribute(&nsm, cudaDevAttrMultiProcessorCount, 0);
    if (nsm <= 0) nsm = 148;
    int grid = 2 * nsm;
    if (grid > N_TILES_TOTAL) grid = N_TILES_TOTAL;

    lstm_pack_kernel<<<BB + NTOT, 512>>>(input, hx, wih, whh, bias);

    cudaFuncSetAttribute(lstm_gemm_kernel,
                         cudaFuncAttributeMaxDynamicSharedMemorySize, SMEM_TOTAL);
    lstm_gemm_kernel<<<grid, 256, SMEM_TOTAL>>>(mA, mW, cx, out);
}